// round 11
// baseline (speedup 1.0000x reference)
#include <cuda_runtime.h>
#include <cuda_bf16.h>
#include <math.h>
#include <stdint.h>

// Problem constants
#define B_   8
#define N_   4096
#define C_   640
#define S_   77
#define XD_  768
#define H_   8
#define DH_  80
#define K_   2
#define BETA_ 0.5f
#define TAU_  0.1f
#define EPS_  1e-8f

#define M_TOT (B_ * N_)   // 32768

// ---------------- scratch (device globals, no allocation) ----------------
__device__ float g_q[(size_t)B_ * N_ * C_];      // q result
__device__ float g_attn[(size_t)B_ * N_ * C_];   // attention output (rounded)
__device__ float g_t1[(size_t)B_ * N_ * C_];     // hsT, later attnT (K-major A operand)
__device__ float g_k[(size_t)B_ * S_ * C_];
__device__ float g_v[(size_t)B_ * S_ * C_];
__device__ float g_wq[C_ * C_];                  // tf32-rounded Wq
__device__ float g_wo[C_ * C_];                  // tf32-rounded Wo
__device__ float g_uhat[S_ * C_];
__device__ float g_ahat[S_ * C_];
__device__ float g_ginv[S_ * 3];

// ---------------- packed f32x2 helpers ----------------
__device__ __forceinline__ void fma2(uint64_t& d, uint64_t a, uint64_t b) {
    asm("fma.rn.f32x2 %0, %1, %2, %0;" : "+l"(d) : "l"(a), "l"(b));
}
__device__ __forceinline__ uint64_t dup2(float x) {
    uint64_t r;
    asm("mov.b64 %0, {%1, %1};" : "=l"(r) : "f"(x));
    return r;
}
__device__ __forceinline__ float2 unpk(uint64_t v) {
    float2 r;
    asm("mov.b64 {%0, %1}, %2;" : "=f"(r.x), "=f"(r.y) : "l"(v));
    return r;
}
__device__ __forceinline__ float to_tf32(float x) {
    uint32_t r;
    asm("cvt.rna.tf32.f32 %0, %1;" : "=r"(r) : "f"(x));
    return __uint_as_float(r);
}

// ---------------- mbarrier / bulk-copy helpers ----------------
__device__ __forceinline__ void mbar_init(uint32_t mbar, uint32_t count) {
    asm volatile("mbarrier.init.shared.b64 [%0], %1;" :: "r"(mbar), "r"(count) : "memory");
}
__device__ __forceinline__ void mbar_expect_tx(uint32_t mbar, uint32_t bytes) {
    asm volatile("mbarrier.arrive.expect_tx.shared.b64 _, [%0], %1;"
                 :: "r"(mbar), "r"(bytes) : "memory");
}
__device__ __forceinline__ void bulk_g2s(uint32_t dst, const void* src, uint32_t bytes,
                                         uint32_t mbar) {
    asm volatile(
        "cp.async.bulk.shared::cta.global.mbarrier::complete_tx::bytes [%0], [%1], %2, [%3];"
        :: "r"(dst), "l"(src), "r"(bytes), "r"(mbar) : "memory");
}
__device__ __forceinline__ void mbar_wait(uint32_t mbar, uint32_t phase) {
    asm volatile(
        "{\n\t"
        ".reg .pred P;\n\t"
        "WAIT_%=:\n\t"
        "mbarrier.try_wait.parity.acquire.cta.shared::cta.b64 P, [%0], %1, 0x989680;\n\t"
        "@P bra DONE_%=;\n\t"
        "bra WAIT_%=;\n\t"
        "DONE_%=:\n\t"
        "}"
        :: "r"(mbar), "r"(phase) : "memory");
}

// ---------------- tf32 rounding pass (weights) ----------------
__global__ __launch_bounds__(256)
void round_tf32_kernel(const float* __restrict__ src, float* __restrict__ dst, int n4) {
    const int i = blockIdx.x * 256 + threadIdx.x;
    if (i < n4) {
        float4 v = reinterpret_cast<const float4*>(src)[i];
        v.x = to_tf32(v.x); v.y = to_tf32(v.y);
        v.z = to_tf32(v.z); v.w = to_tf32(v.w);
        reinterpret_cast<float4*>(dst)[i] = v;
    }
}

// ---------------- 32x32 tiled transpose, optional tf32 rounding ----------
// src[Mrows][Ncols] -> dst[Ncols][Mrows]. Mrows%32==0, Ncols%32==0.
__global__ __launch_bounds__(256)
void transpose_kernel(const float* __restrict__ src, float* __restrict__ dst,
                      int Mrows, int Ncols, int doRound) {
    __shared__ float tile[32][33];
    const int bx = blockIdx.x * 32;    // col base
    const int by = blockIdx.y * 32;    // row base
    const int tx = threadIdx.x & 31;
    const int ty = threadIdx.x >> 5;   // 0..7
#pragma unroll
    for (int i = 0; i < 32; i += 8) {
        float v = src[(size_t)(by + ty + i) * Ncols + bx + tx];
        tile[ty + i][tx] = doRound ? to_tf32(v) : v;
    }
    __syncthreads();
#pragma unroll
    for (int i = 0; i < 32; i += 8) {
        dst[(size_t)(bx + ty + i) * Mrows + by + tx] = tile[tx][ty + i];
    }
}

// ================= tf32 tensor-core GEMM, bulk-copy pipeline =================
// C[M,N] = A^T-stored @ B[K,N] (+bias).
// At is K-major: At[k][m], ldAt = M. A and B MUST be pre-rounded to tf32.
// M%128==0, N%128==0, K%16==0.
#define TBM 128
#define TBN 128
#define TBK 16
#define NSTAGE 3
#define T_STRIDE 136     // floats per smem tile row (128 data + 8 pad)
#define GEMM_SMEM (NSTAGE * 2 * TBK * T_STRIDE * 4)

__global__ __launch_bounds__(256, 2)
void tf32_gemm_kernel(const float* __restrict__ At, const float* __restrict__ Bm,
                      float* __restrict__ Cm, const float* __restrict__ bias,
                      int M, int N, int K)
{
    extern __shared__ float smem[];
    float* sA = smem;                              // [NSTAGE][TBK][T_STRIDE]
    float* sB = smem + NSTAGE * TBK * T_STRIDE;    // [NSTAGE][TBK][T_STRIDE]
    __shared__ __align__(8) uint64_t mbars[NSTAGE];

    const int tid  = threadIdx.x;
    const int wid  = tid >> 5;
    const int lane = tid & 31;
    const int g    = lane >> 2;
    const int tg   = lane & 3;
    const int wm   = (wid & 1) * 64;
    const int wn   = (wid >> 1) * 32;
    const int row0 = blockIdx.y * TBM;
    const int col0 = blockIdx.x * TBN;

    const int NT = K / TBK;

    const uint32_t sA_u32 = (uint32_t)__cvta_generic_to_shared(sA);
    const uint32_t sB_u32 = (uint32_t)__cvta_generic_to_shared(sB);
    const uint32_t mb0    = (uint32_t)__cvta_generic_to_shared(mbars);

    if (tid == 0) {
#pragma unroll
        for (int s = 0; s < NSTAGE; s++) mbar_init(mb0 + s * 8, 32);
    }
    __syncthreads();

    // 32 bulk copies per tile: threads 0-15 A rows, 16-31 B rows, 512B each.
    auto issue = [&](int t) {
        if (t < NT && tid < 32) {
            const int st = t % NSTAGE;
            const uint32_t mb = mb0 + st * 8;
            const int k0 = t * TBK;
            mbar_expect_tx(mb, 512);
            if (tid < 16) {
                bulk_g2s(sA_u32 + ((st * TBK + tid) * T_STRIDE) * 4,
                         At + (size_t)(k0 + tid) * M + row0, 512, mb);
            } else {
                const int bk = tid - 16;
                bulk_g2s(sB_u32 + ((st * TBK + bk) * T_STRIDE) * 4,
                         Bm + (size_t)(k0 + bk) * N + col0, 512, mb);
            }
        }
    };

    float acc[4][4][4];
#pragma unroll
    for (int mt = 0; mt < 4; mt++)
#pragma unroll
        for (int nt = 0; nt < 4; nt++)
#pragma unroll
            for (int e = 0; e < 4; e++) acc[mt][nt][e] = 0.f;

    issue(0);
    issue(1);

#pragma unroll 1
    for (int t = 0; t < NT; t++) {
        const int st = t % NSTAGE;
        mbar_wait(mb0 + st * 8, (t / NSTAGE) & 1);   // stage t resident
        __syncthreads();                             // all done reading stage (t-1)%3
        issue(t + 2);                                // refill (t+2)%3 == (t-1)%3

        const float* As = sA + st * TBK * T_STRIDE;  // [k][m]
        const float* Bs = sB + st * TBK * T_STRIDE;  // [k][n]

#pragma unroll
        for (int ks = 0; ks < 2; ks++) {
            const int kk = ks * 8;
            uint32_t af[4][4];
#pragma unroll
            for (int mt = 0; mt < 4; mt++) {
                const int r = wm + mt * 16;
                af[mt][0] = __float_as_uint(As[(kk + tg) * T_STRIDE + r + g]);
                af[mt][1] = __float_as_uint(As[(kk + tg) * T_STRIDE + r + g + 8]);
                af[mt][2] = __float_as_uint(As[(kk + tg + 4) * T_STRIDE + r + g]);
                af[mt][3] = __float_as_uint(As[(kk + tg + 4) * T_STRIDE + r + g + 8]);
            }
            uint32_t bf[4][2];
#pragma unroll
            for (int nt = 0; nt < 4; nt++) {
                const int c = wn + nt * 8 + g;
                bf[nt][0] = __float_as_uint(Bs[(kk + tg) * T_STRIDE + c]);
                bf[nt][1] = __float_as_uint(Bs[(kk + tg + 4) * T_STRIDE + c]);
            }
#pragma unroll
            for (int mt = 0; mt < 4; mt++)
#pragma unroll
                for (int nt = 0; nt < 4; nt++) {
                    asm volatile(
                        "mma.sync.aligned.m16n8k8.row.col.f32.tf32.tf32.f32 "
                        "{%0,%1,%2,%3}, {%4,%5,%6,%7}, {%8,%9}, {%0,%1,%2,%3};"
                        : "+f"(acc[mt][nt][0]), "+f"(acc[mt][nt][1]),
                          "+f"(acc[mt][nt][2]), "+f"(acc[mt][nt][3])
                        : "r"(af[mt][0]), "r"(af[mt][1]), "r"(af[mt][2]), "r"(af[mt][3]),
                          "r"(bf[nt][0]), "r"(bf[nt][1]));
                }
        }
    }

#pragma unroll
    for (int mt = 0; mt < 4; mt++) {
        const int r_hi = row0 + wm + mt * 16 + g;
#pragma unroll
        for (int nt = 0; nt < 4; nt++) {
            const int cc = col0 + wn + nt * 8 + 2 * tg;
            float2 v0 = make_float2(acc[mt][nt][0], acc[mt][nt][1]);
            float2 v1 = make_float2(acc[mt][nt][2], acc[mt][nt][3]);
            if (bias) {
                const float b0 = bias[cc], b1 = bias[cc + 1];
                v0.x += b0; v0.y += b1;
                v1.x += b0; v1.y += b1;
            }
            *reinterpret_cast<float2*>(Cm + (size_t)r_hi * N + cc) = v0;
            *reinterpret_cast<float2*>(Cm + (size_t)(r_hi + 8) * N + cc) = v1;
        }
    }
}

// ---------------- fp32 SGEMM body for k/v proj ----------
template<int BM, int BN, int TM, int TN>
__device__ __forceinline__ void sgemm_body(
    const float* __restrict__ A, const float* __restrict__ Bm,
    float* __restrict__ Cm, const float* __restrict__ bias,
    int M, int N, int K, int rowStart, int colStart)
{
    constexpr int BK = 8;
    __shared__ float As[BK][BM + 4];
    __shared__ float Bs[BK][BN];

    const int tid = threadIdx.x;
    constexpr int TX = BN / TN;
    const int tx = tid % TX;
    const int ty = tid / TX;

    constexpr int ALOADS = BM * BK / 4;
    constexpr int BLOADS = BN * BK / 4;
    constexpr int AREG = (ALOADS + 255) / 256;
    constexpr int BREG = (BLOADS + 255) / 256;

    float4 ra[AREG], rb[BREG];

    auto loadA = [&](int k0) {
#pragma unroll
        for (int i = 0; i < AREG; i++) {
            const int t = tid + i * 256;
            if ((ALOADS % 256 == 0) || t < ALOADS) {
                const int r = rowStart + (t >> 1);
                const int kk = k0 + (t & 1) * 4;
                ra[i] = (r < M) ? *reinterpret_cast<const float4*>(A + (size_t)r * K + kk)
                                : make_float4(0.f, 0.f, 0.f, 0.f);
            }
        }
    };
    auto storeA = [&]() {
#pragma unroll
        for (int i = 0; i < AREG; i++) {
            const int t = tid + i * 256;
            if ((ALOADS % 256 == 0) || t < ALOADS) {
                const int r = t >> 1;
                const int kk = (t & 1) * 4;
                As[kk + 0][r] = ra[i].x;
                As[kk + 1][r] = ra[i].y;
                As[kk + 2][r] = ra[i].z;
                As[kk + 3][r] = ra[i].w;
            }
        }
    };
    auto loadB = [&](int k0) {
#pragma unroll
        for (int i = 0; i < BREG; i++) {
            const int t = tid + i * 256;
            if ((BLOADS % 256 == 0) || t < BLOADS) {
                const int kr = t / (BN / 4);
                const int cq = (t % (BN / 4)) * 4;
                rb[i] = *reinterpret_cast<const float4*>(
                    Bm + (size_t)(k0 + kr) * N + colStart + cq);
            }
        }
    };
    auto storeB = [&]() {
#pragma unroll
        for (int i = 0; i < BREG; i++) {
            const int t = tid + i * 256;
            if ((BLOADS % 256 == 0) || t < BLOADS) {
                const int kr = t / (BN / 4);
                const int cq = (t % (BN / 4)) * 4;
                *reinterpret_cast<float4*>(&Bs[kr][cq]) = rb[i];
            }
        }
    };

    uint64_t acc[TM][TN / 2];
#pragma unroll
    for (int i = 0; i < TM; i++)
#pragma unroll
        for (int j = 0; j < TN / 2; j++) acc[i][j] = 0ull;

    loadA(0);
    loadB(0);

    for (int k0 = 0; k0 < K; k0 += BK) {
        storeA();
        storeB();
        __syncthreads();
        if (k0 + BK < K) {
            loadA(k0 + BK);
            loadB(k0 + BK);
        }
#pragma unroll
        for (int kk = 0; kk < BK; kk++) {
            uint64_t a2[TM], b2[TN / 2];
#pragma unroll
            for (int i = 0; i < TM; i++) a2[i] = dup2(As[kk][ty * TM + i]);
#pragma unroll
            for (int j = 0; j < TN / 2; j++)
                b2[j] = *reinterpret_cast<const uint64_t*>(&Bs[kk][tx * TN + 2 * j]);
#pragma unroll
            for (int i = 0; i < TM; i++)
#pragma unroll
                for (int j = 0; j < TN / 2; j++) fma2(acc[i][j], a2[i], b2[j]);
        }
        __syncthreads();
    }

#pragma unroll
    for (int i = 0; i < TM; i++) {
        const int gr = rowStart + ty * TM + i;
        if (gr >= M) continue;
#pragma unroll
        for (int j = 0; j < TN / 2; j++) {
            const int gc = colStart + tx * TN + 2 * j;
            float2 v = unpk(acc[i][j]);
            if (bias) {
                v.x += bias[gc + 0];
                v.y += bias[gc + 1];
            }
            *reinterpret_cast<float2*>(Cm + (size_t)gr * N + gc) = v;
        }
    }
}

__global__ __launch_bounds__(256)
void kv_kernel(const float* __restrict__ enc, const float* __restrict__ Wk,
               const float* __restrict__ Wv) {
    const float* Bm = blockIdx.z ? Wv : Wk;
    float* Cm = blockIdx.z ? g_v : g_k;
    sgemm_body<64, 64, 4, 4>(enc, Bm, Cm, nullptr, B_ * S_, C_, XD_,
                             blockIdx.y * 64, blockIdx.x * 64);
}

// ---------------- block reduction helper ----------------
__device__ __forceinline__ float block_reduce_sum(float val, float* red) {
    const int lane = threadIdx.x & 31;
    const int w = threadIdx.x >> 5;
#pragma unroll
    for (int o = 16; o; o >>= 1) val += __shfl_xor_sync(0xffffffffu, val, o);
    if (lane == 0) red[w] = val;
    __syncthreads();
    float v = (threadIdx.x < 8) ? red[threadIdx.x] : 0.f;
    if (w == 0) {
#pragma unroll
        for (int o = 4; o; o >>= 1) v += __shfl_xor_sync(0xffffffffu, v, o);
        if (lane == 0) red[0] = v;
    }
    __syncthreads();
    float out = red[0];
    __syncthreads();
    return out;
}

// ---------------- CORA prep ----------------
__global__ __launch_bounds__(256)
void cora_prep_kernel(const float* __restrict__ target, const float* __restrict__ anchor,
                      const float* __restrict__ preserve) {
    const int s = blockIdx.x;
    const int tid = threadIdx.x;

    __shared__ float sp0[C_], sp1[C_], st[C_], sa[C_], su[C_], saa[C_];
    __shared__ float red[8];

    for (int d = tid; d < C_; d += 256) {
        sp0[d] = preserve[(size_t)0 * S_ * C_ + (size_t)s * C_ + d];
        sp1[d] = preserve[(size_t)1 * S_ * C_ + (size_t)s * C_ + d];
        st[d]  = target[(size_t)s * C_ + d];
        sa[d]  = anchor[(size_t)s * C_ + d];
    }
    __syncthreads();

    float g00 = 0.f, g01 = 0.f, g11 = 0.f;
    float bt0 = 0.f, bt1 = 0.f, ba0 = 0.f, ba1 = 0.f;
    for (int d = tid; d < C_; d += 256) {
        const float p0 = sp0[d], p1 = sp1[d], t = st[d], a = sa[d];
        g00 += p0 * p0; g01 += p0 * p1; g11 += p1 * p1;
        bt0 += p0 * t;  bt1 += p1 * t;
        ba0 += p0 * a;  ba1 += p1 * a;
    }
    g00 = block_reduce_sum(g00, red);
    g01 = block_reduce_sum(g01, red);
    g11 = block_reduce_sum(g11, red);
    bt0 = block_reduce_sum(bt0, red);
    bt1 = block_reduce_sum(bt1, red);
    ba0 = block_reduce_sum(ba0, red);
    ba1 = block_reduce_sum(ba1, red);

    const float det = g00 * g11 - g01 * g01;
    const float i00 = g11 / det, i01 = -g01 / det, i11 = g00 / det;

    const float ct0 = i00 * bt0 + i01 * bt1;
    const float ct1 = i01 * bt0 + i11 * bt1;
    const float ca0 = i00 * ba0 + i01 * ba1;
    const float ca1 = i01 * ba0 + i11 * ba1;

    float nu = 0.f;
    for (int d = tid; d < C_; d += 256) {
        const float u = st[d] - sp0[d] * ct0 - sp1[d] * ct1;
        su[d] = u;
        nu += u * u;
    }
    __syncthreads();
    nu = block_reduce_sum(nu, red);
    const float inv_nu = 1.f / (sqrtf(nu) + EPS_);
    for (int d = tid; d < C_; d += 256) su[d] *= inv_nu;
    __syncthreads();

    float dot = 0.f;
    for (int d = tid; d < C_; d += 256) {
        const float ad = sa[d] - sp0[d] * ca0 - sp1[d] * ca1;
        saa[d] = ad;
        dot += su[d] * ad;
    }
    __syncthreads();
    dot = block_reduce_sum(dot, red);
    float na = 0.f;
    for (int d = tid; d < C_; d += 256) {
        const float at = saa[d] - dot * su[d];
        saa[d] = at;
        na += at * at;
    }
    __syncthreads();
    na = block_reduce_sum(na, red);
    const float inv_na = 1.f / (sqrtf(na) + EPS_);

    for (int d = tid; d < C_; d += 256) {
        g_uhat[(size_t)s * C_ + d] = su[d];
        g_ahat[(size_t)s * C_ + d] = saa[d] * inv_na;
    }
    if (tid == 0) {
        g_ginv[s * 3 + 0] = i00;
        g_ginv[s * 3 + 1] = i01;
        g_ginv[s * 3 + 2] = i11;
    }
}

// ---------------- CORA apply ----------------
__global__ __launch_bounds__(256)
void cora_apply_kernel(const float* __restrict__ preserve) {
    const int bs = blockIdx.x;
    const int s = bs % S_;
    const int tid = threadIdx.x;
    float* vrow = g_v + (size_t)bs * C_;

    __shared__ float sp0[C_], sp1[C_], sv[C_];
    __shared__ float red[8];

    for (int d = tid; d < C_; d += 256) {
        sp0[d] = preserve[(size_t)0 * S_ * C_ + (size_t)s * C_ + d];
        sp1[d] = preserve[(size_t)1 * S_ * C_ + (size_t)s * C_ + d];
        sv[d]  = vrow[d];
    }
    __syncthreads();

    float b0 = 0.f, b1 = 0.f;
    for (int d = tid; d < C_; d += 256) {
        b0 += sp0[d] * sv[d];
        b1 += sp1[d] * sv[d];
    }
    b0 = block_reduce_sum(b0, red);
    b1 = block_reduce_sum(b1, red);

    const float i00 = g_ginv[s * 3 + 0], i01 = g_ginv[s * 3 + 1], i11 = g_ginv[s * 3 + 2];
    const float c0 = i00 * b0 + i01 * b1;
    const float c1 = i01 * b0 + i11 * b1;

    float t = 0.f, nn = 0.f;
    for (int d = tid; d < C_; d += 256) {
        const float vf = sv[d] - sp0[d] * c0 - sp1[d] * c1;
        t += g_uhat[(size_t)s * C_ + d] * vf;
        nn += vf * vf;
    }
    t  = block_reduce_sum(t, red);
    nn = block_reduce_sum(nn, red);

    const float denom = sqrtf(nn) + EPS_;
    const bool keep = (fabsf(t) / denom) < TAU_;
    if (!keep) {
        for (int d = tid; d < C_; d += 256) {
            vrow[d] = sv[d] - t * g_uhat[(size_t)s * C_ + d]
                            + BETA_ * t * g_ahat[(size_t)s * C_ + d];
        }
    }
}

// ---------------- fused attention: per (b, h, 32 q-rows) ----------------
#define RQ 32
#define SKP 82   // padded head dim

__global__ __launch_bounds__(256)
void attn_kernel() {
    extern __shared__ float sm[];
    float* sq = sm;                      // RQ * SKP
    float* sk = sq + RQ * SKP;           // S_ * SKP
    float* sv = sk + S_ * SKP;           // S_ * SKP
    float* sp = sv + S_ * SKP;           // RQ * 80

    const int b = blockIdx.z;
    const int h = blockIdx.y;
    const int n0 = blockIdx.x * RQ;
    const int tid = threadIdx.x;

    for (int t = tid; t < RQ * 20; t += 256) {
        const int r = t / 20, dq = (t % 20) * 4;
        float4 v = *reinterpret_cast<const float4*>(
            g_q + ((size_t)b * N_ + (n0 + r)) * C_ + h * DH_ + dq);
        float* dst = &sq[r * SKP + dq];
        dst[0] = v.x; dst[1] = v.y; dst[2] = v.z; dst[3] = v.w;
    }
    for (int t = tid; t < S_ * 20; t += 256) {
        const int s = t / 20, dq = (t % 20) * 4;
        const size_t off = ((size_t)b * S_ + s) * C_ + h * DH_ + dq;
        float4 kk4 = *reinterpret_cast<const float4*>(g_k + off);
        float4 vv4 = *reinterpret_cast<const float4*>(g_v + off);
        float* dk = &sk[s * SKP + dq];
        dk[0] = kk4.x; dk[1] = kk4.y; dk[2] = kk4.z; dk[3] = kk4.w;
        float* dv = &sv[s * SKP + dq];
        dv[0] = vv4.x; dv[1] = vv4.y; dv[2] = vv4.z; dv[3] = vv4.w;
    }
    __syncthreads();

    // stage 1: scores
    {
        const int r1 = tid >> 3;
        const int s0 = (tid & 7) * 10;
        uint64_t acc2[10];
#pragma unroll
        for (int i = 0; i < 10; i++) acc2[i] = 0ull;
        const float* qrow = sq + r1 * SKP;
        const float* krow = sk + s0 * SKP;
#pragma unroll 8
        for (int d2 = 0; d2 < 40; d2++) {
            const uint64_t q2 = *reinterpret_cast<const uint64_t*>(qrow + 2 * d2);
#pragma unroll
            for (int i = 0; i < 10; i++) {
                const uint64_t k2 = *reinterpret_cast<const uint64_t*>(krow + i * SKP + 2 * d2);
                fma2(acc2[i], q2, k2);
            }
        }
        const float scale = 0.11180339887498948f;   // 1/sqrt(80)
#pragma unroll
        for (int i = 0; i < 10; i++) {
            const int s = s0 + i;
            if (s < S_) {
                float2 u = unpk(acc2[i]);
                sp[r1 * 80 + s] = (u.x + u.y) * scale;
            }
        }
    }
    __syncthreads();

    // stage 2: softmax
    {
        const int warp = tid >> 5, lane = tid & 31;
        for (int r = warp; r < RQ; r += 8) {
            float m = -INFINITY;
            for (int s = lane; s < S_; s += 32) m = fmaxf(m, sp[r * 80 + s]);
#pragma unroll
            for (int o = 16; o; o >>= 1) m = fmaxf(m, __shfl_xor_sync(0xffffffffu, m, o));
            float sum = 0.f;
            for (int s = lane; s < S_; s += 32) {
                const float e = __expf(sp[r * 80 + s] - m);
                sp[r * 80 + s] = e;
                sum += e;
            }
#pragma unroll
            for (int o = 16; o; o >>= 1) sum += __shfl_xor_sync(0xffffffffu, sum, o);
            const float inv = 1.f / sum;
            for (int s = lane; s < S_; s += 32) sp[r * 80 + s] *= inv;
        }
    }
    __syncthreads();

    // stage 3: out = probs @ V — outputs pre-rounded to tf32 for the out-proj GEMM
    {
        const int r3 = tid >> 3;
        const int d0 = (tid & 7) * 10;
        uint64_t acc3[5];
#pragma unroll
        for (int j = 0; j < 5; j++) acc3[j] = 0ull;
        const float* prow = sp + r3 * 80;
#pragma unroll 7
        for (int s = 0; s < S_; s++) {
            const uint64_t p2 = dup2(prow[s]);
            const float* vrow = sv + s * SKP + d0;
#pragma unroll
            for (int j = 0; j < 5; j++) {
                const uint64_t v2 = *reinterpret_cast<const uint64_t*>(vrow + 2 * j);
                fma2(acc3[j], p2, v2);
            }
        }
        float* orow = g_attn + ((size_t)b * N_ + (n0 + r3)) * C_ + h * DH_ + d0;
#pragma unroll
        for (int j = 0; j < 5; j++) {
            float2 v = unpk(acc3[j]);
            v.x = to_tf32(v.x);
            v.y = to_tf32(v.y);
            *reinterpret_cast<float2*>(orow + 2 * j) = v;
        }
    }
}

// ---------------- launch ----------------
extern "C" void kernel_launch(void* const* d_in, const int* in_sizes, int n_in,
                              void* d_out, int out_size) {
    const float* hs       = (const float*)d_in[0];
    const float* enc      = (const float*)d_in[1];
    const float* Wq       = (const float*)d_in[2];
    const float* Wk       = (const float*)d_in[3];
    const float* Wv       = (const float*)d_in[4];
    const float* Wo       = (const float*)d_in[5];
    const float* bo       = (const float*)d_in[6];
    const float* target   = (const float*)d_in[7];
    const float* anchor   = (const float*)d_in[8];
    const float* preserve = (const float*)d_in[9];
    float* out = (float*)d_out;

    float *pq, *pattn, *pt1, *pwq, *pwo;
    cudaGetSymbolAddress((void**)&pq, g_q);
    cudaGetSymbolAddress((void**)&pattn, g_attn);
    cudaGetSymbolAddress((void**)&pt1, g_t1);
    cudaGetSymbolAddress((void**)&pwq, g_wq);
    cudaGetSymbolAddress((void**)&pwo, g_wo);

    static bool s_init = false;
    if (!s_init) {
        cudaFuncSetAttribute(tf32_gemm_kernel,
                             cudaFuncAttributeMaxDynamicSharedMemorySize, GEMM_SMEM);
        s_init = true;
    }

    // round weights; round+transpose hs -> g_t1 (hsT, K-major)
    {
        const int n4_w = (C_ * C_) / 4;
        round_tf32_kernel<<<(n4_w + 255) / 256, 256>>>(Wq, pwq, n4_w);
        round_tf32_kernel<<<(n4_w + 255) / 256, 256>>>(Wo, pwo, n4_w);
        dim3 tg(C_ / 32, M_TOT / 32);
        transpose_kernel<<<tg, 256>>>(hs, pt1, M_TOT, C_, 1);
    }

    // q = round(hs) @ round(Wq) — bulk-copy tf32 GEMM (A = hsT)
    {
        dim3 grid(C_ / TBN, M_TOT / TBM);
        tf32_gemm_kernel<<<grid, 256, GEMM_SMEM>>>(pt1, pwq, pq, nullptr,
                                                   M_TOT, C_, C_);
    }
    // k/v = enc @ {Wk, Wv} — exact fp32
    {
        dim3 grid(C_ / 64, (B_ * S_ + 63) / 64, 2);
        kv_kernel<<<grid, 256>>>(enc, Wk, Wv);
    }
    // CORA erase on v
    cora_prep_kernel<<<S_, 256>>>(target, anchor, preserve);
    cora_apply_kernel<<<B_ * S_, 256>>>(preserve);

    // fused attention (fp32, writes tf32-rounded outputs into g_attn)
    {
        const int smem_bytes = (RQ * SKP + 2 * S_ * SKP + RQ * 80) * (int)sizeof(float);
        cudaFuncSetAttribute(attn_kernel, cudaFuncAttributeMaxDynamicSharedMemorySize,
                             smem_bytes);
        dim3 grid(N_ / RQ, H_, B_);
        attn_kernel<<<grid, 256, smem_bytes>>>();
    }

    // transpose attn output -> g_t1 (attnT), then out = attn @ round(Wo) + bo
    {
        dim3 tg(C_ / 32, M_TOT / 32);
        transpose_kernel<<<tg, 256>>>(pattn, pt1, M_TOT, C_, 0);
        dim3 grid(C_ / TBN, M_TOT / TBM);
        tf32_gemm_kernel<<<grid, 256, GEMM_SMEM>>>(pt1, pwo, out, bo,
                                                   M_TOT, C_, C_);
    }
}

// round 13
// speedup vs baseline: 1.3426x; 1.3426x over previous
#include <cuda_runtime.h>
#include <cuda_bf16.h>
#include <math.h>
#include <stdint.h>

// Problem constants
#define B_   8
#define N_   4096
#define C_   640
#define S_   77
#define XD_  768
#define H_   8
#define DH_  80
#define K_   2
#define BETA_ 0.5f
#define TAU_  0.1f
#define EPS_  1e-8f

// ---------------- scratch (device globals, no allocation) ----------------
__device__ float g_q[(size_t)B_ * N_ * C_];
__device__ float g_attn[(size_t)B_ * N_ * C_];
__device__ float g_k[(size_t)B_ * S_ * C_];
__device__ float g_v[(size_t)B_ * S_ * C_];
__device__ float g_uhat[S_ * C_];
__device__ float g_ahat[S_ * C_];
__device__ float g_ginv[S_ * 3];

// ---------------- packed f32x2 helpers ----------------
__device__ __forceinline__ void fma2(uint64_t& d, uint64_t a, uint64_t b) {
    asm("fma.rn.f32x2 %0, %1, %2, %0;" : "+l"(d) : "l"(a), "l"(b));
}
__device__ __forceinline__ uint64_t dup2(float x) {
    uint64_t r;
    asm("mov.b64 %0, {%1, %1};" : "=l"(r) : "f"(x));
    return r;
}
__device__ __forceinline__ float2 unpk(uint64_t v) {
    float2 r;
    asm("mov.b64 {%0, %1}, %2;" : "=f"(r.x), "=f"(r.y) : "l"(v));
    return r;
}
__device__ __forceinline__ float to_tf32(float x) {
    uint32_t r;
    asm("cvt.rna.tf32.f32 %0, %1;" : "=r"(r) : "f"(x));
    return __uint_as_float(r);
}

// ================= tf32 tensor-core GEMM (round-7 config: single buffer) ====
#define TBM 128
#define TBN 128
#define TBK 16

__global__ __launch_bounds__(256, 2)
void tf32_gemm_kernel(const float* __restrict__ A, const float* __restrict__ Bm,
                      float* __restrict__ Cm, const float* __restrict__ bias,
                      int M, int N, int K)
{
    __shared__ float As[TBM][20];
    __shared__ float Bs[TBK][136];

    const int tid  = threadIdx.x;
    const int wid  = tid >> 5;
    const int lane = tid & 31;
    const int g    = lane >> 2;
    const int tg   = lane & 3;
    const int wm   = (wid & 1) * 64;
    const int wn   = (wid >> 1) * 32;
    const int row0 = blockIdx.y * TBM;
    const int col0 = blockIdx.x * TBN;

    const int a_r0 = tid >> 2;
    const int a_c  = (tid & 3) * 4;
    const int b_k0 = tid >> 5;
    const int b_c  = (tid & 31) * 4;

    float4 ra[2], rb[2];
    auto loadG = [&](int k0) {
        ra[0] = *reinterpret_cast<const float4*>(A + (size_t)(row0 + a_r0) * K + k0 + a_c);
        ra[1] = *reinterpret_cast<const float4*>(A + (size_t)(row0 + a_r0 + 64) * K + k0 + a_c);
        rb[0] = *reinterpret_cast<const float4*>(Bm + (size_t)(k0 + b_k0) * N + col0 + b_c);
        rb[1] = *reinterpret_cast<const float4*>(Bm + (size_t)(k0 + b_k0 + 8) * N + col0 + b_c);
    };
    auto storeS = [&]() {
#pragma unroll
        for (int i = 0; i < 2; i++) {
            float* da = &As[a_r0 + i * 64][a_c];
            da[0] = to_tf32(ra[i].x); da[1] = to_tf32(ra[i].y);
            da[2] = to_tf32(ra[i].z); da[3] = to_tf32(ra[i].w);
            float* db = &Bs[b_k0 + i * 8][b_c];
            db[0] = to_tf32(rb[i].x); db[1] = to_tf32(rb[i].y);
            db[2] = to_tf32(rb[i].z); db[3] = to_tf32(rb[i].w);
        }
    };

    float acc[4][4][4];
#pragma unroll
    for (int mt = 0; mt < 4; mt++)
#pragma unroll
        for (int nt = 0; nt < 4; nt++)
#pragma unroll
            for (int e = 0; e < 4; e++) acc[mt][nt][e] = 0.f;

    loadG(0);

    for (int k0 = 0; k0 < K; k0 += TBK) {
        storeS();
        __syncthreads();
        if (k0 + TBK < K) loadG(k0 + TBK);

#pragma unroll
        for (int ks = 0; ks < 2; ks++) {
            const int kk = ks * 8;
            uint32_t af[4][4];
#pragma unroll
            for (int mt = 0; mt < 4; mt++) {
                const int r = wm + mt * 16;
                af[mt][0] = __float_as_uint(As[r + g][kk + tg]);
                af[mt][1] = __float_as_uint(As[r + g + 8][kk + tg]);
                af[mt][2] = __float_as_uint(As[r + g][kk + tg + 4]);
                af[mt][3] = __float_as_uint(As[r + g + 8][kk + tg + 4]);
            }
            uint32_t bf[4][2];
#pragma unroll
            for (int nt = 0; nt < 4; nt++) {
                const int c = wn + nt * 8 + g;
                bf[nt][0] = __float_as_uint(Bs[kk + tg][c]);
                bf[nt][1] = __float_as_uint(Bs[kk + tg + 4][c]);
            }
#pragma unroll
            for (int mt = 0; mt < 4; mt++)
#pragma unroll
                for (int nt = 0; nt < 4; nt++) {
                    asm volatile(
                        "mma.sync.aligned.m16n8k8.row.col.f32.tf32.tf32.f32 "
                        "{%0,%1,%2,%3}, {%4,%5,%6,%7}, {%8,%9}, {%0,%1,%2,%3};"
                        : "+f"(acc[mt][nt][0]), "+f"(acc[mt][nt][1]),
                          "+f"(acc[mt][nt][2]), "+f"(acc[mt][nt][3])
                        : "r"(af[mt][0]), "r"(af[mt][1]), "r"(af[mt][2]), "r"(af[mt][3]),
                          "r"(bf[nt][0]), "r"(bf[nt][1]));
                }
        }
        __syncthreads();
    }

#pragma unroll
    for (int mt = 0; mt < 4; mt++) {
        const int r_hi = row0 + wm + mt * 16 + g;
#pragma unroll
        for (int nt = 0; nt < 4; nt++) {
            const int cc = col0 + wn + nt * 8 + 2 * tg;
            float2 v0 = make_float2(acc[mt][nt][0], acc[mt][nt][1]);
            float2 v1 = make_float2(acc[mt][nt][2], acc[mt][nt][3]);
            if (bias) {
                const float b0 = bias[cc], b1 = bias[cc + 1];
                v0.x += b0; v0.y += b1;
                v1.x += b0; v1.y += b1;
            }
            *reinterpret_cast<float2*>(Cm + (size_t)r_hi * N + cc) = v0;
            *reinterpret_cast<float2*>(Cm + (size_t)(r_hi + 8) * N + cc) = v1;
        }
    }
}

// ---------------- fp32 SGEMM body for k/v proj ----------
template<int BM, int BN, int TM, int TN>
__device__ __forceinline__ void sgemm_body(
    const float* __restrict__ A, const float* __restrict__ Bm,
    float* __restrict__ Cm, const float* __restrict__ bias,
    int M, int N, int K, int rowStart, int colStart)
{
    constexpr int BK = 8;
    __shared__ float As[BK][BM + 4];
    __shared__ float Bs[BK][BN];

    const int tid = threadIdx.x;
    constexpr int TX = BN / TN;
    const int tx = tid % TX;
    const int ty = tid / TX;

    constexpr int ALOADS = BM * BK / 4;
    constexpr int BLOADS = BN * BK / 4;
    constexpr int AREG = (ALOADS + 255) / 256;
    constexpr int BREG = (BLOADS + 255) / 256;

    float4 ra[AREG], rb[BREG];

    auto loadA = [&](int k0) {
#pragma unroll
        for (int i = 0; i < AREG; i++) {
            const int t = tid + i * 256;
            if ((ALOADS % 256 == 0) || t < ALOADS) {
                const int r = rowStart + (t >> 1);
                const int kk = k0 + (t & 1) * 4;
                ra[i] = (r < M) ? *reinterpret_cast<const float4*>(A + (size_t)r * K + kk)
                                : make_float4(0.f, 0.f, 0.f, 0.f);
            }
        }
    };
    auto storeA = [&]() {
#pragma unroll
        for (int i = 0; i < AREG; i++) {
            const int t = tid + i * 256;
            if ((ALOADS % 256 == 0) || t < ALOADS) {
                const int r = t >> 1;
                const int kk = (t & 1) * 4;
                As[kk + 0][r] = ra[i].x;
                As[kk + 1][r] = ra[i].y;
                As[kk + 2][r] = ra[i].z;
                As[kk + 3][r] = ra[i].w;
            }
        }
    };
    auto loadB = [&](int k0) {
#pragma unroll
        for (int i = 0; i < BREG; i++) {
            const int t = tid + i * 256;
            if ((BLOADS % 256 == 0) || t < BLOADS) {
                const int kr = t / (BN / 4);
                const int cq = (t % (BN / 4)) * 4;
                rb[i] = *reinterpret_cast<const float4*>(
                    Bm + (size_t)(k0 + kr) * N + colStart + cq);
            }
        }
    };
    auto storeB = [&]() {
#pragma unroll
        for (int i = 0; i < BREG; i++) {
            const int t = tid + i * 256;
            if ((BLOADS % 256 == 0) || t < BLOADS) {
                const int kr = t / (BN / 4);
                const int cq = (t % (BN / 4)) * 4;
                *reinterpret_cast<float4*>(&Bs[kr][cq]) = rb[i];
            }
        }
    };

    uint64_t acc[TM][TN / 2];
#pragma unroll
    for (int i = 0; i < TM; i++)
#pragma unroll
        for (int j = 0; j < TN / 2; j++) acc[i][j] = 0ull;

    loadA(0);
    loadB(0);

    for (int k0 = 0; k0 < K; k0 += BK) {
        storeA();
        storeB();
        __syncthreads();
        if (k0 + BK < K) {
            loadA(k0 + BK);
            loadB(k0 + BK);
        }
#pragma unroll
        for (int kk = 0; kk < BK; kk++) {
            uint64_t a2[TM], b2[TN / 2];
#pragma unroll
            for (int i = 0; i < TM; i++) a2[i] = dup2(As[kk][ty * TM + i]);
#pragma unroll
            for (int j = 0; j < TN / 2; j++)
                b2[j] = *reinterpret_cast<const uint64_t*>(&Bs[kk][tx * TN + 2 * j]);
#pragma unroll
            for (int i = 0; i < TM; i++)
#pragma unroll
                for (int j = 0; j < TN / 2; j++) fma2(acc[i][j], a2[i], b2[j]);
        }
        __syncthreads();
    }

#pragma unroll
    for (int i = 0; i < TM; i++) {
        const int gr = rowStart + ty * TM + i;
        if (gr >= M) continue;
#pragma unroll
        for (int j = 0; j < TN / 2; j++) {
            const int gc = colStart + tx * TN + 2 * j;
            float2 v = unpk(acc[i][j]);
            if (bias) {
                v.x += bias[gc + 0];
                v.y += bias[gc + 1];
            }
            *reinterpret_cast<float2*>(Cm + (size_t)gr * N + gc) = v;
        }
    }
}

__global__ __launch_bounds__(256)
void kv_kernel(const float* __restrict__ enc, const float* __restrict__ Wk,
               const float* __restrict__ Wv) {
    const float* Bm = blockIdx.z ? Wv : Wk;
    float* Cm = blockIdx.z ? g_v : g_k;
    sgemm_body<64, 64, 4, 4>(enc, Bm, Cm, nullptr, B_ * S_, C_, XD_,
                             blockIdx.y * 64, blockIdx.x * 64);
}

// ---------------- block reduction helper ----------------
__device__ __forceinline__ float block_reduce_sum(float val, float* red) {
    const int lane = threadIdx.x & 31;
    const int w = threadIdx.x >> 5;
#pragma unroll
    for (int o = 16; o; o >>= 1) val += __shfl_xor_sync(0xffffffffu, val, o);
    if (lane == 0) red[w] = val;
    __syncthreads();
    float v = (threadIdx.x < 8) ? red[threadIdx.x] : 0.f;
    if (w == 0) {
#pragma unroll
        for (int o = 4; o; o >>= 1) v += __shfl_xor_sync(0xffffffffu, v, o);
        if (lane == 0) red[0] = v;
    }
    __syncthreads();
    float out = red[0];
    __syncthreads();
    return out;
}

// ---------------- CORA prep ----------------
__global__ __launch_bounds__(256)
void cora_prep_kernel(const float* __restrict__ target, const float* __restrict__ anchor,
                      const float* __restrict__ preserve) {
    const int s = blockIdx.x;
    const int tid = threadIdx.x;

    __shared__ float sp0[C_], sp1[C_], st[C_], sa[C_], su[C_], saa[C_];
    __shared__ float red[8];

    for (int d = tid; d < C_; d += 256) {
        sp0[d] = preserve[(size_t)0 * S_ * C_ + (size_t)s * C_ + d];
        sp1[d] = preserve[(size_t)1 * S_ * C_ + (size_t)s * C_ + d];
        st[d]  = target[(size_t)s * C_ + d];
        sa[d]  = anchor[(size_t)s * C_ + d];
    }
    __syncthreads();

    float g00 = 0.f, g01 = 0.f, g11 = 0.f;
    float bt0 = 0.f, bt1 = 0.f, ba0 = 0.f, ba1 = 0.f;
    for (int d = tid; d < C_; d += 256) {
        const float p0 = sp0[d], p1 = sp1[d], t = st[d], a = sa[d];
        g00 += p0 * p0; g01 += p0 * p1; g11 += p1 * p1;
        bt0 += p0 * t;  bt1 += p1 * t;
        ba0 += p0 * a;  ba1 += p1 * a;
    }
    g00 = block_reduce_sum(g00, red);
    g01 = block_reduce_sum(g01, red);
    g11 = block_reduce_sum(g11, red);
    bt0 = block_reduce_sum(bt0, red);
    bt1 = block_reduce_sum(bt1, red);
    ba0 = block_reduce_sum(ba0, red);
    ba1 = block_reduce_sum(ba1, red);

    const float det = g00 * g11 - g01 * g01;
    const float i00 = g11 / det, i01 = -g01 / det, i11 = g00 / det;

    const float ct0 = i00 * bt0 + i01 * bt1;
    const float ct1 = i01 * bt0 + i11 * bt1;
    const float ca0 = i00 * ba0 + i01 * ba1;
    const float ca1 = i01 * ba0 + i11 * ba1;

    float nu = 0.f;
    for (int d = tid; d < C_; d += 256) {
        const float u = st[d] - sp0[d] * ct0 - sp1[d] * ct1;
        su[d] = u;
        nu += u * u;
    }
    __syncthreads();
    nu = block_reduce_sum(nu, red);
    const float inv_nu = 1.f / (sqrtf(nu) + EPS_);
    for (int d = tid; d < C_; d += 256) su[d] *= inv_nu;
    __syncthreads();

    float dot = 0.f;
    for (int d = tid; d < C_; d += 256) {
        const float ad = sa[d] - sp0[d] * ca0 - sp1[d] * ca1;
        saa[d] = ad;
        dot += su[d] * ad;
    }
    __syncthreads();
    dot = block_reduce_sum(dot, red);
    float na = 0.f;
    for (int d = tid; d < C_; d += 256) {
        const float at = saa[d] - dot * su[d];
        saa[d] = at;
        na += at * at;
    }
    __syncthreads();
    na = block_reduce_sum(na, red);
    const float inv_na = 1.f / (sqrtf(na) + EPS_);

    for (int d = tid; d < C_; d += 256) {
        g_uhat[(size_t)s * C_ + d] = su[d];
        g_ahat[(size_t)s * C_ + d] = saa[d] * inv_na;
    }
    if (tid == 0) {
        g_ginv[s * 3 + 0] = i00;
        g_ginv[s * 3 + 1] = i01;
        g_ginv[s * 3 + 2] = i11;
    }
}

// ---------------- CORA apply ----------------
__global__ __launch_bounds__(256)
void cora_apply_kernel(const float* __restrict__ preserve) {
    const int bs = blockIdx.x;
    const int s = bs % S_;
    const int tid = threadIdx.x;
    float* vrow = g_v + (size_t)bs * C_;

    __shared__ float sp0[C_], sp1[C_], sv[C_];
    __shared__ float red[8];

    for (int d = tid; d < C_; d += 256) {
        sp0[d] = preserve[(size_t)0 * S_ * C_ + (size_t)s * C_ + d];
        sp1[d] = preserve[(size_t)1 * S_ * C_ + (size_t)s * C_ + d];
        sv[d]  = vrow[d];
    }
    __syncthreads();

    float b0 = 0.f, b1 = 0.f;
    for (int d = tid; d < C_; d += 256) {
        b0 += sp0[d] * sv[d];
        b1 += sp1[d] * sv[d];
    }
    b0 = block_reduce_sum(b0, red);
    b1 = block_reduce_sum(b1, red);

    const float i00 = g_ginv[s * 3 + 0], i01 = g_ginv[s * 3 + 1], i11 = g_ginv[s * 3 + 2];
    const float c0 = i00 * b0 + i01 * b1;
    const float c1 = i01 * b0 + i11 * b1;

    float t = 0.f, nn = 0.f;
    for (int d = tid; d < C_; d += 256) {
        const float vf = sv[d] - sp0[d] * c0 - sp1[d] * c1;
        t += g_uhat[(size_t)s * C_ + d] * vf;
        nn += vf * vf;
    }
    t  = block_reduce_sum(t, red);
    nn = block_reduce_sum(nn, red);

    const float denom = sqrtf(nn) + EPS_;
    const bool keep = (fabsf(t) / denom) < TAU_;
    if (!keep) {
        for (int d = tid; d < C_; d += 256) {
            vrow[d] = sv[d] - t * g_uhat[(size_t)s * C_ + d]
                            + BETA_ * t * g_ahat[(size_t)s * C_ + d];
        }
    }
}

// ---------------- fused attention: per (b, h, 32 q-rows) ----------------
// Register-blocked: stage 1 = 128 threads x (4 rows x 5 keys),
//                   stage 3 = 128 threads x (2 rows x 10 d).
#define RQ 32
#define SKP 82    // padded head dim (even -> 8B-aligned rows)
#define SKROWS 80 // padded key-row count (s<77 guard discards the rest)

__global__ __launch_bounds__(256)
void attn_kernel() {
    extern __shared__ float sm[];
    float* sq = sm;                      // RQ * SKP
    float* sk = sq + RQ * SKP;           // SKROWS * SKP (rows 77..79 garbage, guarded)
    float* sv = sk + SKROWS * SKP;       // S_ * SKP
    float* sp = sv + S_ * SKP;           // RQ * 80

    const int b = blockIdx.z;
    const int h = blockIdx.y;
    const int n0 = blockIdx.x * RQ;
    const int tid = threadIdx.x;

    for (int t = tid; t < RQ * 20; t += 256) {
        const int r = t / 20, dq = (t % 20) * 4;
        float4 v = *reinterpret_cast<const float4*>(
            g_q + ((size_t)b * N_ + (n0 + r)) * C_ + h * DH_ + dq);
        float* dst = &sq[r * SKP + dq];
        dst[0] = v.x; dst[1] = v.y; dst[2] = v.z; dst[3] = v.w;
    }
    for (int t = tid; t < S_ * 20; t += 256) {
        const int s = t / 20, dq = (t % 20) * 4;
        const size_t off = ((size_t)b * S_ + s) * C_ + h * DH_ + dq;
        float4 kk4 = *reinterpret_cast<const float4*>(g_k + off);
        float4 vv4 = *reinterpret_cast<const float4*>(g_v + off);
        float* dk = &sk[s * SKP + dq];
        dk[0] = kk4.x; dk[1] = kk4.y; dk[2] = kk4.z; dk[3] = kk4.w;
        float* dv = &sv[s * SKP + dq];
        dv[0] = vv4.x; dv[1] = vv4.y; dv[2] = vv4.z; dv[3] = vv4.w;
    }
    __syncthreads();

    // stage 1: scores — 128 threads, each 4 rows x 5 keys (f32x2 over d)
    if (tid < 128) {
        const int r0 = (tid >> 4) * 4;       // 8 groups x 4 rows
        const int s0 = (tid & 15) * 5;       // 16 groups x 5 keys (covers 80)
        uint64_t acc[4][5];
#pragma unroll
        for (int i = 0; i < 4; i++)
#pragma unroll
            for (int j = 0; j < 5; j++) acc[i][j] = 0ull;

        const float* qb = sq + r0 * SKP;
        const float* kb = sk + s0 * SKP;
#pragma unroll 4
        for (int d2 = 0; d2 < 40; d2++) {
            uint64_t q2[4], k2[5];
#pragma unroll
            for (int i = 0; i < 4; i++)
                q2[i] = *reinterpret_cast<const uint64_t*>(qb + i * SKP + 2 * d2);
#pragma unroll
            for (int j = 0; j < 5; j++)
                k2[j] = *reinterpret_cast<const uint64_t*>(kb + j * SKP + 2 * d2);
#pragma unroll
            for (int i = 0; i < 4; i++)
#pragma unroll
                for (int j = 0; j < 5; j++) fma2(acc[i][j], q2[i], k2[j]);
        }
        const float scale = 0.11180339887498948f;   // 1/sqrt(80)
#pragma unroll
        for (int i = 0; i < 4; i++)
#pragma unroll
            for (int j = 0; j < 5; j++) {
                const int s = s0 + j;
                if (s < S_) {
                    float2 u = unpk(acc[i][j]);
                    sp[(r0 + i) * 80 + s] = (u.x + u.y) * scale;
                }
            }
    }
    __syncthreads();

    // stage 2: softmax (one warp per row, 4 rows per warp)
    {
        const int warp = tid >> 5, lane = tid & 31;
        for (int r = warp; r < RQ; r += 8) {
            float m = -INFINITY;
            for (int s = lane; s < S_; s += 32) m = fmaxf(m, sp[r * 80 + s]);
#pragma unroll
            for (int o = 16; o; o >>= 1) m = fmaxf(m, __shfl_xor_sync(0xffffffffu, m, o));
            float sum = 0.f;
            for (int s = lane; s < S_; s += 32) {
                const float e = __expf(sp[r * 80 + s] - m);
                sp[r * 80 + s] = e;
                sum += e;
            }
#pragma unroll
            for (int o = 16; o; o >>= 1) sum += __shfl_xor_sync(0xffffffffu, sum, o);
            const float inv = 1.f / sum;
            for (int s = lane; s < S_; s += 32) sp[r * 80 + s] *= inv;
        }
    }
    __syncthreads();

    // stage 3: out = probs @ V — 128 threads, each 2 rows x 10 d
    if (tid < 128) {
        const int r0 = (tid >> 3) * 2;       // 16 groups x 2 rows
        const int d0 = (tid & 7) * 10;       // 8 groups x 10 floats (5 pairs)
        uint64_t acc0[5], acc1[5];
#pragma unroll
        for (int j = 0; j < 5; j++) { acc0[j] = 0ull; acc1[j] = 0ull; }
        const float* p0p = sp + r0 * 80;
        const float* p1p = sp + (r0 + 1) * 80;
#pragma unroll 7
        for (int s = 0; s < S_; s++) {
            const uint64_t p0 = dup2(p0p[s]);
            const uint64_t p1 = dup2(p1p[s]);
            const float* vrow = sv + s * SKP + d0;
#pragma unroll
            for (int j = 0; j < 5; j++) {
                const uint64_t v2 = *reinterpret_cast<const uint64_t*>(vrow + 2 * j);
                fma2(acc0[j], p0, v2);
                fma2(acc1[j], p1, v2);
            }
        }
        float* o0 = g_attn + ((size_t)b * N_ + (n0 + r0)) * C_ + h * DH_ + d0;
        float* o1 = g_attn + ((size_t)b * N_ + (n0 + r0 + 1)) * C_ + h * DH_ + d0;
#pragma unroll
        for (int j = 0; j < 5; j++) {
            *reinterpret_cast<float2*>(o0 + 2 * j) = unpk(acc0[j]);
            *reinterpret_cast<float2*>(o1 + 2 * j) = unpk(acc1[j]);
        }
    }
}

// ---------------- launch ----------------
extern "C" void kernel_launch(void* const* d_in, const int* in_sizes, int n_in,
                              void* d_out, int out_size) {
    const float* hs       = (const float*)d_in[0];
    const float* enc      = (const float*)d_in[1];
    const float* Wq       = (const float*)d_in[2];
    const float* Wk       = (const float*)d_in[3];
    const float* Wv       = (const float*)d_in[4];
    const float* Wo       = (const float*)d_in[5];
    const float* bo       = (const float*)d_in[6];
    const float* target   = (const float*)d_in[7];
    const float* anchor   = (const float*)d_in[8];
    const float* preserve = (const float*)d_in[9];
    float* out = (float*)d_out;

    float *pq, *pattn;
    cudaGetSymbolAddress((void**)&pq, g_q);
    cudaGetSymbolAddress((void**)&pattn, g_attn);

    // q = hs @ Wq — tf32 tensor cores
    {
        dim3 grid(C_ / TBN, (B_ * N_) / TBM);
        tf32_gemm_kernel<<<grid, 256>>>(hs, Wq, pq, nullptr, B_ * N_, C_, C_);
    }
    // k/v = enc @ {Wk, Wv} — exact fp32
    {
        dim3 grid(C_ / 64, (B_ * S_ + 63) / 64, 2);
        kv_kernel<<<grid, 256>>>(enc, Wk, Wv);
    }
    // CORA erase on v
    cora_prep_kernel<<<S_, 256>>>(target, anchor, preserve);
    cora_apply_kernel<<<B_ * S_, 256>>>(preserve);

    // fused attention (fp32, register-blocked)
    {
        const int smem_bytes = (RQ * SKP + SKROWS * SKP + S_ * SKP + RQ * 80)
                               * (int)sizeof(float);
        cudaFuncSetAttribute(attn_kernel, cudaFuncAttributeMaxDynamicSharedMemorySize,
                             smem_bytes);
        dim3 grid(N_ / RQ, H_, B_);
        attn_kernel<<<grid, 256, smem_bytes>>>();
    }

    // out = attn @ Wo + bo — tf32 tensor cores
    {
        dim3 grid(C_ / TBN, (B_ * N_) / TBM);
        tf32_gemm_kernel<<<grid, 256>>>(pattn, Wo, out, bo, B_ * N_, C_, C_);
    }
}

// round 15
// speedup vs baseline: 1.3493x; 1.0050x over previous
#include <cuda_runtime.h>
#include <cuda_bf16.h>
#include <math.h>
#include <stdint.h>

// Problem constants
#define B_   8
#define N_   4096
#define C_   640
#define S_   77
#define XD_  768
#define H_   8
#define DH_  80
#define K_   2
#define BETA_ 0.5f
#define TAU_  0.1f
#define EPS_  1e-8f

// ---------------- scratch (device globals, no allocation) ----------------
__device__ float g_q[(size_t)B_ * N_ * C_];
__device__ float g_attn[(size_t)B_ * N_ * C_];
__device__ float g_k[(size_t)B_ * S_ * C_];
__device__ float g_v[(size_t)B_ * S_ * C_];
__device__ float g_uhat[S_ * C_];
__device__ float g_ahat[S_ * C_];
__device__ float g_ginv[S_ * 3];

// ---------------- packed f32x2 helpers ----------------
__device__ __forceinline__ void fma2(uint64_t& d, uint64_t a, uint64_t b) {
    asm("fma.rn.f32x2 %0, %1, %2, %0;" : "+l"(d) : "l"(a), "l"(b));
}
__device__ __forceinline__ uint64_t dup2(float x) {
    uint64_t r;
    asm("mov.b64 %0, {%1, %1};" : "=l"(r) : "f"(x));
    return r;
}
__device__ __forceinline__ float2 unpk(uint64_t v) {
    float2 r;
    asm("mov.b64 {%0, %1}, %2;" : "=f"(r.x), "=f"(r.y) : "l"(v));
    return r;
}
__device__ __forceinline__ float to_tf32(float x) {
    uint32_t r;
    asm("cvt.rna.tf32.f32 %0, %1;" : "=r"(r) : "f"(x));
    return __uint_as_float(r);
}

// ================= tf32 tensor-core GEMM (round-7 config) ====
#define TBM 128
#define TBN 128
#define TBK 16

__global__ __launch_bounds__(256, 2)
void tf32_gemm_kernel(const float* __restrict__ A, const float* __restrict__ Bm,
                      float* __restrict__ Cm, const float* __restrict__ bias,
                      int M, int N, int K)
{
    __shared__ float As[TBM][20];
    __shared__ float Bs[TBK][136];

    const int tid  = threadIdx.x;
    const int wid  = tid >> 5;
    const int lane = tid & 31;
    const int g    = lane >> 2;
    const int tg   = lane & 3;
    const int wm   = (wid & 1) * 64;
    const int wn   = (wid >> 1) * 32;
    const int row0 = blockIdx.y * TBM;
    const int col0 = blockIdx.x * TBN;

    const int a_r0 = tid >> 2;
    const int a_c  = (tid & 3) * 4;
    const int b_k0 = tid >> 5;
    const int b_c  = (tid & 31) * 4;

    float4 ra[2], rb[2];
    auto loadG = [&](int k0) {
        ra[0] = *reinterpret_cast<const float4*>(A + (size_t)(row0 + a_r0) * K + k0 + a_c);
        ra[1] = *reinterpret_cast<const float4*>(A + (size_t)(row0 + a_r0 + 64) * K + k0 + a_c);
        rb[0] = *reinterpret_cast<const float4*>(Bm + (size_t)(k0 + b_k0) * N + col0 + b_c);
        rb[1] = *reinterpret_cast<const float4*>(Bm + (size_t)(k0 + b_k0 + 8) * N + col0 + b_c);
    };
    auto storeS = [&]() {
#pragma unroll
        for (int i = 0; i < 2; i++) {
            float* da = &As[a_r0 + i * 64][a_c];
            da[0] = to_tf32(ra[i].x); da[1] = to_tf32(ra[i].y);
            da[2] = to_tf32(ra[i].z); da[3] = to_tf32(ra[i].w);
            float* db = &Bs[b_k0 + i * 8][b_c];
            db[0] = to_tf32(rb[i].x); db[1] = to_tf32(rb[i].y);
            db[2] = to_tf32(rb[i].z); db[3] = to_tf32(rb[i].w);
        }
    };

    float acc[4][4][4];
#pragma unroll
    for (int mt = 0; mt < 4; mt++)
#pragma unroll
        for (int nt = 0; nt < 4; nt++)
#pragma unroll
            for (int e = 0; e < 4; e++) acc[mt][nt][e] = 0.f;

    loadG(0);

    for (int k0 = 0; k0 < K; k0 += TBK) {
        storeS();
        __syncthreads();
        if (k0 + TBK < K) loadG(k0 + TBK);

#pragma unroll
        for (int ks = 0; ks < 2; ks++) {
            const int kk = ks * 8;
            uint32_t af[4][4];
#pragma unroll
            for (int mt = 0; mt < 4; mt++) {
                const int r = wm + mt * 16;
                af[mt][0] = __float_as_uint(As[r + g][kk + tg]);
                af[mt][1] = __float_as_uint(As[r + g + 8][kk + tg]);
                af[mt][2] = __float_as_uint(As[r + g][kk + tg + 4]);
                af[mt][3] = __float_as_uint(As[r + g + 8][kk + tg + 4]);
            }
            uint32_t bf[4][2];
#pragma unroll
            for (int nt = 0; nt < 4; nt++) {
                const int c = wn + nt * 8 + g;
                bf[nt][0] = __float_as_uint(Bs[kk + tg][c]);
                bf[nt][1] = __float_as_uint(Bs[kk + tg + 4][c]);
            }
#pragma unroll
            for (int mt = 0; mt < 4; mt++)
#pragma unroll
                for (int nt = 0; nt < 4; nt++) {
                    asm volatile(
                        "mma.sync.aligned.m16n8k8.row.col.f32.tf32.tf32.f32 "
                        "{%0,%1,%2,%3}, {%4,%5,%6,%7}, {%8,%9}, {%0,%1,%2,%3};"
                        : "+f"(acc[mt][nt][0]), "+f"(acc[mt][nt][1]),
                          "+f"(acc[mt][nt][2]), "+f"(acc[mt][nt][3])
                        : "r"(af[mt][0]), "r"(af[mt][1]), "r"(af[mt][2]), "r"(af[mt][3]),
                          "r"(bf[nt][0]), "r"(bf[nt][1]));
                }
        }
        __syncthreads();
    }

#pragma unroll
    for (int mt = 0; mt < 4; mt++) {
        const int r_hi = row0 + wm + mt * 16 + g;
#pragma unroll
        for (int nt = 0; nt < 4; nt++) {
            const int cc = col0 + wn + nt * 8 + 2 * tg;
            float2 v0 = make_float2(acc[mt][nt][0], acc[mt][nt][1]);
            float2 v1 = make_float2(acc[mt][nt][2], acc[mt][nt][3]);
            if (bias) {
                const float b0 = bias[cc], b1 = bias[cc + 1];
                v0.x += b0; v0.y += b1;
                v1.x += b0; v1.y += b1;
            }
            *reinterpret_cast<float2*>(Cm + (size_t)r_hi * N + cc) = v0;
            *reinterpret_cast<float2*>(Cm + (size_t)(r_hi + 8) * N + cc) = v1;
        }
    }
}

// ---------------- fp32 SGEMM body for k/v proj ----------
template<int BM, int BN, int TM, int TN>
__device__ __forceinline__ void sgemm_body(
    const float* __restrict__ A, const float* __restrict__ Bm,
    float* __restrict__ Cm, const float* __restrict__ bias,
    int M, int N, int K, int rowStart, int colStart)
{
    constexpr int BK = 8;
    __shared__ float As[BK][BM + 4];
    __shared__ float Bs[BK][BN];

    const int tid = threadIdx.x;
    constexpr int TX = BN / TN;
    const int tx = tid % TX;
    const int ty = tid / TX;

    constexpr int ALOADS = BM * BK / 4;
    constexpr int BLOADS = BN * BK / 4;
    constexpr int AREG = (ALOADS + 255) / 256;
    constexpr int BREG = (BLOADS + 255) / 256;

    float4 ra[AREG], rb[BREG];

    auto loadA = [&](int k0) {
#pragma unroll
        for (int i = 0; i < AREG; i++) {
            const int t = tid + i * 256;
            if ((ALOADS % 256 == 0) || t < ALOADS) {
                const int r = rowStart + (t >> 1);
                const int kk = k0 + (t & 1) * 4;
                ra[i] = (r < M) ? *reinterpret_cast<const float4*>(A + (size_t)r * K + kk)
                                : make_float4(0.f, 0.f, 0.f, 0.f);
            }
        }
    };
    auto storeA = [&]() {
#pragma unroll
        for (int i = 0; i < AREG; i++) {
            const int t = tid + i * 256;
            if ((ALOADS % 256 == 0) || t < ALOADS) {
                const int r = t >> 1;
                const int kk = (t & 1) * 4;
                As[kk + 0][r] = ra[i].x;
                As[kk + 1][r] = ra[i].y;
                As[kk + 2][r] = ra[i].z;
                As[kk + 3][r] = ra[i].w;
            }
        }
    };
    auto loadB = [&](int k0) {
#pragma unroll
        for (int i = 0; i < BREG; i++) {
            const int t = tid + i * 256;
            if ((BLOADS % 256 == 0) || t < BLOADS) {
                const int kr = t / (BN / 4);
                const int cq = (t % (BN / 4)) * 4;
                rb[i] = *reinterpret_cast<const float4*>(
                    Bm + (size_t)(k0 + kr) * N + colStart + cq);
            }
        }
    };
    auto storeB = [&]() {
#pragma unroll
        for (int i = 0; i < BREG; i++) {
            const int t = tid + i * 256;
            if ((BLOADS % 256 == 0) || t < BLOADS) {
                const int kr = t / (BN / 4);
                const int cq = (t % (BN / 4)) * 4;
                *reinterpret_cast<float4*>(&Bs[kr][cq]) = rb[i];
            }
        }
    };

    uint64_t acc[TM][TN / 2];
#pragma unroll
    for (int i = 0; i < TM; i++)
#pragma unroll
        for (int j = 0; j < TN / 2; j++) acc[i][j] = 0ull;

    loadA(0);
    loadB(0);

    for (int k0 = 0; k0 < K; k0 += BK) {
        storeA();
        storeB();
        __syncthreads();
        if (k0 + BK < K) {
            loadA(k0 + BK);
            loadB(k0 + BK);
        }
#pragma unroll
        for (int kk = 0; kk < BK; kk++) {
            uint64_t a2[TM], b2[TN / 2];
#pragma unroll
            for (int i = 0; i < TM; i++) a2[i] = dup2(As[kk][ty * TM + i]);
#pragma unroll
            for (int j = 0; j < TN / 2; j++)
                b2[j] = *reinterpret_cast<const uint64_t*>(&Bs[kk][tx * TN + 2 * j]);
#pragma unroll
            for (int i = 0; i < TM; i++)
#pragma unroll
                for (int j = 0; j < TN / 2; j++) fma2(acc[i][j], a2[i], b2[j]);
        }
        __syncthreads();
    }

#pragma unroll
    for (int i = 0; i < TM; i++) {
        const int gr = rowStart + ty * TM + i;
        if (gr >= M) continue;
#pragma unroll
        for (int j = 0; j < TN / 2; j++) {
            const int gc = colStart + tx * TN + 2 * j;
            float2 v = unpk(acc[i][j]);
            if (bias) {
                v.x += bias[gc + 0];
                v.y += bias[gc + 1];
            }
            *reinterpret_cast<float2*>(Cm + (size_t)gr * N + gc) = v;
        }
    }
}

__global__ __launch_bounds__(256)
void kv_kernel(const float* __restrict__ enc, const float* __restrict__ Wk,
               const float* __restrict__ Wv) {
    const float* Bm = blockIdx.z ? Wv : Wk;
    float* Cm = blockIdx.z ? g_v : g_k;
    sgemm_body<64, 64, 4, 4>(enc, Bm, Cm, nullptr, B_ * S_, C_, XD_,
                             blockIdx.y * 64, blockIdx.x * 64);
}

// ---------------- block reduction helper ----------------
__device__ __forceinline__ float block_reduce_sum(float val, float* red) {
    const int lane = threadIdx.x & 31;
    const int w = threadIdx.x >> 5;
#pragma unroll
    for (int o = 16; o; o >>= 1) val += __shfl_xor_sync(0xffffffffu, val, o);
    if (lane == 0) red[w] = val;
    __syncthreads();
    float v = (threadIdx.x < 8) ? red[threadIdx.x] : 0.f;
    if (w == 0) {
#pragma unroll
        for (int o = 4; o; o >>= 1) v += __shfl_xor_sync(0xffffffffu, v, o);
        if (lane == 0) red[0] = v;
    }
    __syncthreads();
    float out = red[0];
    __syncthreads();
    return out;
}

// ---------------- CORA prep ----------------
__global__ __launch_bounds__(256)
void cora_prep_kernel(const float* __restrict__ target, const float* __restrict__ anchor,
                      const float* __restrict__ preserve) {
    const int s = blockIdx.x;
    const int tid = threadIdx.x;

    __shared__ float sp0[C_], sp1[C_], st[C_], sa[C_], su[C_], saa[C_];
    __shared__ float red[8];

    for (int d = tid; d < C_; d += 256) {
        sp0[d] = preserve[(size_t)0 * S_ * C_ + (size_t)s * C_ + d];
        sp1[d] = preserve[(size_t)1 * S_ * C_ + (size_t)s * C_ + d];
        st[d]  = target[(size_t)s * C_ + d];
        sa[d]  = anchor[(size_t)s * C_ + d];
    }
    __syncthreads();

    float g00 = 0.f, g01 = 0.f, g11 = 0.f;
    float bt0 = 0.f, bt1 = 0.f, ba0 = 0.f, ba1 = 0.f;
    for (int d = tid; d < C_; d += 256) {
        const float p0 = sp0[d], p1 = sp1[d], t = st[d], a = sa[d];
        g00 += p0 * p0; g01 += p0 * p1; g11 += p1 * p1;
        bt0 += p0 * t;  bt1 += p1 * t;
        ba0 += p0 * a;  ba1 += p1 * a;
    }
    g00 = block_reduce_sum(g00, red);
    g01 = block_reduce_sum(g01, red);
    g11 = block_reduce_sum(g11, red);
    bt0 = block_reduce_sum(bt0, red);
    bt1 = block_reduce_sum(bt1, red);
    ba0 = block_reduce_sum(ba0, red);
    ba1 = block_reduce_sum(ba1, red);

    const float det = g00 * g11 - g01 * g01;
    const float i00 = g11 / det, i01 = -g01 / det, i11 = g00 / det;

    const float ct0 = i00 * bt0 + i01 * bt1;
    const float ct1 = i01 * bt0 + i11 * bt1;
    const float ca0 = i00 * ba0 + i01 * ba1;
    const float ca1 = i01 * ba0 + i11 * ba1;

    float nu = 0.f;
    for (int d = tid; d < C_; d += 256) {
        const float u = st[d] - sp0[d] * ct0 - sp1[d] * ct1;
        su[d] = u;
        nu += u * u;
    }
    __syncthreads();
    nu = block_reduce_sum(nu, red);
    const float inv_nu = 1.f / (sqrtf(nu) + EPS_);
    for (int d = tid; d < C_; d += 256) su[d] *= inv_nu;
    __syncthreads();

    float dot = 0.f;
    for (int d = tid; d < C_; d += 256) {
        const float ad = sa[d] - sp0[d] * ca0 - sp1[d] * ca1;
        saa[d] = ad;
        dot += su[d] * ad;
    }
    __syncthreads();
    dot = block_reduce_sum(dot, red);
    float na = 0.f;
    for (int d = tid; d < C_; d += 256) {
        const float at = saa[d] - dot * su[d];
        saa[d] = at;
        na += at * at;
    }
    __syncthreads();
    na = block_reduce_sum(na, red);
    const float inv_na = 1.f / (sqrtf(na) + EPS_);

    for (int d = tid; d < C_; d += 256) {
        g_uhat[(size_t)s * C_ + d] = su[d];
        g_ahat[(size_t)s * C_ + d] = saa[d] * inv_na;
    }
    if (tid == 0) {
        g_ginv[s * 3 + 0] = i00;
        g_ginv[s * 3 + 1] = i01;
        g_ginv[s * 3 + 2] = i11;
    }
}

// ---------------- CORA apply ----------------
__global__ __launch_bounds__(256)
void cora_apply_kernel(const float* __restrict__ preserve) {
    const int bs = blockIdx.x;
    const int s = bs % S_;
    const int tid = threadIdx.x;
    float* vrow = g_v + (size_t)bs * C_;

    __shared__ float sp0[C_], sp1[C_], sv[C_];
    __shared__ float red[8];

    for (int d = tid; d < C_; d += 256) {
        sp0[d] = preserve[(size_t)0 * S_ * C_ + (size_t)s * C_ + d];
        sp1[d] = preserve[(size_t)1 * S_ * C_ + (size_t)s * C_ + d];
        sv[d]  = vrow[d];
    }
    __syncthreads();

    float b0 = 0.f, b1 = 0.f;
    for (int d = tid; d < C_; d += 256) {
        b0 += sp0[d] * sv[d];
        b1 += sp1[d] * sv[d];
    }
    b0 = block_reduce_sum(b0, red);
    b1 = block_reduce_sum(b1, red);

    const float i00 = g_ginv[s * 3 + 0], i01 = g_ginv[s * 3 + 1], i11 = g_ginv[s * 3 + 2];
    const float c0 = i00 * b0 + i01 * b1;
    const float c1 = i01 * b0 + i11 * b1;

    float t = 0.f, nn = 0.f;
    for (int d = tid; d < C_; d += 256) {
        const float vf = sv[d] - sp0[d] * c0 - sp1[d] * c1;
        t += g_uhat[(size_t)s * C_ + d] * vf;
        nn += vf * vf;
    }
    t  = block_reduce_sum(t, red);
    nn = block_reduce_sum(nn, red);

    const float denom = sqrtf(nn) + EPS_;
    const bool keep = (fabsf(t) / denom) < TAU_;
    if (!keep) {
        for (int d = tid; d < C_; d += 256) {
            vrow[d] = sv[d] - t * g_uhat[(size_t)s * C_ + d]
                            + BETA_ * t * g_ahat[(size_t)s * C_ + d];
        }
    }
}

// ---------------- fused attention: per (b, h, 32 q-rows) ----------------
// stage 1 = tf32 mma (4 warps, 16m x 40n each), stage 3 = 64 thr x (4r x 10d)
#define RQ 32
#define SKP 82     // q / v row stride
#define KTP 84     // skt row stride (bank-clean for tg: {0,20,8,28})

__global__ __launch_bounds__(256)
void attn_kernel() {
    extern __shared__ float sm[];
    float* sq  = sm;                     // RQ * SKP      (tf32-rounded Q, [r][d])
    float* skt = sq + RQ * SKP;          // 80 * KTP      (tf32-rounded K^T, [d][s])
    float* sv  = skt + 80 * KTP;         // S_ * SKP      (exact V, [s][d])
    float* sp  = sv + S_ * SKP;          // RQ * 80       (scores / probs)

    const int b = blockIdx.z;
    const int h = blockIdx.y;
    const int n0 = blockIdx.x * RQ;
    const int tid = threadIdx.x;

    // fill: q (rounded), k (rounded, transposed), v (exact)
    for (int t = tid; t < RQ * 20; t += 256) {
        const int r = t / 20, dq = (t % 20) * 4;
        float4 v = *reinterpret_cast<const float4*>(
            g_q + ((size_t)b * N_ + (n0 + r)) * C_ + h * DH_ + dq);
        float* dst = &sq[r * SKP + dq];
        dst[0] = to_tf32(v.x); dst[1] = to_tf32(v.y);
        dst[2] = to_tf32(v.z); dst[3] = to_tf32(v.w);
    }
    for (int t = tid; t < S_ * 20; t += 256) {
        const int s = t / 20, dq = (t % 20) * 4;
        const size_t off = ((size_t)b * S_ + s) * C_ + h * DH_ + dq;
        float4 kk4 = *reinterpret_cast<const float4*>(g_k + off);
        float4 vv4 = *reinterpret_cast<const float4*>(g_v + off);
        skt[(dq + 0) * KTP + s] = to_tf32(kk4.x);
        skt[(dq + 1) * KTP + s] = to_tf32(kk4.y);
        skt[(dq + 2) * KTP + s] = to_tf32(kk4.z);
        skt[(dq + 3) * KTP + s] = to_tf32(kk4.w);
        float* dv = &sv[s * SKP + dq];
        dv[0] = vv4.x; dv[1] = vv4.y; dv[2] = vv4.z; dv[3] = vv4.w;
    }
    __syncthreads();

    // stage 1: scores via tf32 mma — warps 0..3, warp = (mt, 40-wide n block)
    if (tid < 128) {
        const int wid  = tid >> 5;
        const int lane = tid & 31;
        const int g    = lane >> 2;
        const int tg   = lane & 3;
        const int mt   = wid & 1;          // 0/1 -> rows 0-15 / 16-31
        const int nblk = (wid >> 1) * 40;  // 0 / 40

        float acc[5][4];
#pragma unroll
        for (int nt = 0; nt < 5; nt++)
#pragma unroll
            for (int e = 0; e < 4; e++) acc[nt][e] = 0.f;

#pragma unroll
        for (int ks = 0; ks < 10; ks++) {
            const int kk = ks * 8;
            uint32_t af[4];
            const int r = mt * 16;
            af[0] = __float_as_uint(sq[(r + g) * SKP + kk + tg]);
            af[1] = __float_as_uint(sq[(r + g + 8) * SKP + kk + tg]);
            af[2] = __float_as_uint(sq[(r + g) * SKP + kk + tg + 4]);
            af[3] = __float_as_uint(sq[(r + g + 8) * SKP + kk + tg + 4]);
            uint32_t bf[5][2];
#pragma unroll
            for (int nt = 0; nt < 5; nt++) {
                const int c = nblk + nt * 8 + g;
                bf[nt][0] = __float_as_uint(skt[(kk + tg) * KTP + c]);
                bf[nt][1] = __float_as_uint(skt[(kk + tg + 4) * KTP + c]);
            }
#pragma unroll
            for (int nt = 0; nt < 5; nt++) {
                asm volatile(
                    "mma.sync.aligned.m16n8k8.row.col.f32.tf32.tf32.f32 "
                    "{%0,%1,%2,%3}, {%4,%5,%6,%7}, {%8,%9}, {%0,%1,%2,%3};"
                    : "+f"(acc[nt][0]), "+f"(acc[nt][1]),
                      "+f"(acc[nt][2]), "+f"(acc[nt][3])
                    : "r"(af[0]), "r"(af[1]), "r"(af[2]), "r"(af[3]),
                      "r"(bf[nt][0]), "r"(bf[nt][1]));
            }
        }

        const float scale = 0.11180339887498948f;   // 1/sqrt(80)
        const int rlo = mt * 16 + g;
#pragma unroll
        for (int nt = 0; nt < 5; nt++) {
            const int c0 = nblk + nt * 8 + 2 * tg;
            if (c0 < S_)     sp[rlo * 80 + c0]           = acc[nt][0] * scale;
            if (c0 + 1 < S_) sp[rlo * 80 + c0 + 1]       = acc[nt][1] * scale;
            if (c0 < S_)     sp[(rlo + 8) * 80 + c0]     = acc[nt][2] * scale;
            if (c0 + 1 < S_) sp[(rlo + 8) * 80 + c0 + 1] = acc[nt][3] * scale;
        }
    }
    __syncthreads();

    // stage 2: softmax (one warp per row, 4 rows per warp)
    {
        const int warp = tid >> 5, lane = tid & 31;
        for (int r = warp; r < RQ; r += 8) {
            float m = -INFINITY;
            for (int s = lane; s < S_; s += 32) m = fmaxf(m, sp[r * 80 + s]);
#pragma unroll
            for (int o = 16; o; o >>= 1) m = fmaxf(m, __shfl_xor_sync(0xffffffffu, m, o));
            float sum = 0.f;
            for (int s = lane; s < S_; s += 32) {
                const float e = __expf(sp[r * 80 + s] - m);
                sp[r * 80 + s] = e;
                sum += e;
            }
#pragma unroll
            for (int o = 16; o; o >>= 1) sum += __shfl_xor_sync(0xffffffffu, sum, o);
            const float inv = 1.f / sum;
            for (int s = lane; s < S_; s += 32) sp[r * 80 + s] *= inv;
        }
    }
    __syncthreads();

    // stage 3: out = probs @ V — 64 threads, each 4 rows x 10 d
    if (tid < 64) {
        const int r0 = (tid >> 3) * 4;       // 8 groups x 4 rows
        const int d0 = (tid & 7) * 10;       // 8 groups x 10 floats
        uint64_t acc[4][5];
#pragma unroll
        for (int i = 0; i < 4; i++)
#pragma unroll
            for (int j = 0; j < 5; j++) acc[i][j] = 0ull;

#pragma unroll 7
        for (int s = 0; s < S_; s++) {
            uint64_t p[4];
#pragma unroll
            for (int i = 0; i < 4; i++) p[i] = dup2(sp[(r0 + i) * 80 + s]);
            const float* vrow = sv + s * SKP + d0;
#pragma unroll
            for (int j = 0; j < 5; j++) {
                const uint64_t v2 = *reinterpret_cast<const uint64_t*>(vrow + 2 * j);
#pragma unroll
                for (int i = 0; i < 4; i++) fma2(acc[i][j], p[i], v2);
            }
        }
#pragma unroll
        for (int i = 0; i < 4; i++) {
            float* orow = g_attn + ((size_t)b * N_ + (n0 + r0 + i)) * C_ + h * DH_ + d0;
#pragma unroll
            for (int j = 0; j < 5; j++)
                *reinterpret_cast<float2*>(orow + 2 * j) = unpk(acc[i][j]);
        }
    }
}

// ---------------- launch ----------------
extern "C" void kernel_launch(void* const* d_in, const int* in_sizes, int n_in,
                              void* d_out, int out_size) {
    const float* hs       = (const float*)d_in[0];
    const float* enc      = (const float*)d_in[1];
    const float* Wq       = (const float*)d_in[2];
    const float* Wk       = (const float*)d_in[3];
    const float* Wv       = (const float*)d_in[4];
    const float* Wo       = (const float*)d_in[5];
    const float* bo       = (const float*)d_in[6];
    const float* target   = (const float*)d_in[7];
    const float* anchor   = (const float*)d_in[8];
    const float* preserve = (const float*)d_in[9];
    float* out = (float*)d_out;

    float *pq, *pattn;
    cudaGetSymbolAddress((void**)&pq, g_q);
    cudaGetSymbolAddress((void**)&pattn, g_attn);

    // q = hs @ Wq — tf32 tensor cores
    {
        dim3 grid(C_ / TBN, (B_ * N_) / TBM);
        tf32_gemm_kernel<<<grid, 256>>>(hs, Wq, pq, nullptr, B_ * N_, C_, C_);
    }
    // k/v = enc @ {Wk, Wv} — exact fp32
    {
        dim3 grid(C_ / 64, (B_ * S_ + 63) / 64, 2);
        kv_kernel<<<grid, 256>>>(enc, Wk, Wv);
    }
    // CORA erase on v
    cora_prep_kernel<<<S_, 256>>>(target, anchor, preserve);
    cora_apply_kernel<<<B_ * S_, 256>>>(preserve);

    // fused attention (stage1 tf32 mma, stage3 register-blocked fp32)
    {
        const int smem_bytes = (RQ * SKP + 80 * KTP + S_ * SKP + RQ * 80)
                               * (int)sizeof(float);
        cudaFuncSetAttribute(attn_kernel, cudaFuncAttributeMaxDynamicSharedMemorySize,
                             smem_bytes);
        dim3 grid(N_ / RQ, H_, B_);
        attn_kernel<<<grid, 256, smem_bytes>>>();
    }

    // out = attn @ Wo + bo — tf32 tensor cores
    {
        dim3 grid(C_ / TBN, (B_ * N_) / TBM);
        tf32_gemm_kernel<<<grid, 256>>>(pattn, Wo, out, bo, B_ * N_, C_, C_);
    }
}